// round 1
// baseline (speedup 1.0000x reference)
#include <cuda_runtime.h>
#include <stdint.h>

// Problem constants (fixed by the dataset)
#define NUM_RELS   64
#define NUM_BASES  16
#define IN_F       128
#define OUT_F      128

// Per-relation composed weights: 64 * 128 * 128 floats = 4 MB scratch.
__device__ float g_W[NUM_RELS * IN_F * OUT_F];
// Index-width flags (1 = int64 layout, 0 = int32 layout)
__device__ int g_src64;
__device__ int g_dst64;

// ---------------------------------------------------------------------------
// K0: basis composition  W[r] = sum_b w_comp[r][b] * weight[b]   (+ idx detect)
// ---------------------------------------------------------------------------
__global__ void basis_kernel(const float* __restrict__ weight,
                             const float* __restrict__ w_comp,
                             const void* __restrict__ srcv,
                             const void* __restrict__ dstv) {
    if (blockIdx.x == 0 && threadIdx.x == 0) {
        // Detect whether src/dst buffers are int64 or int32. Values are in
        // [0, 100000), so if int64 (little-endian) every odd u32 word is 0.
        const unsigned* s = (const unsigned*)srcv;
        const unsigned* d = (const unsigned*)dstv;
        int s64 = 1, d64 = 1;
        #pragma unroll
        for (int i = 1; i < 32; i += 2) {
            if (s[i] != 0u) s64 = 0;
            if (d[i] != 0u) d64 = 0;
        }
        g_src64 = s64;
        g_dst64 = d64;
    }
    int gid = blockIdx.x * blockDim.x + threadIdx.x;
    if (gid < NUM_RELS * IN_F * OUT_F) {
        int r  = gid >> 14;         // / (128*128)
        int ko = gid & 16383;
        float acc = 0.0f;
        #pragma unroll
        for (int b = 0; b < NUM_BASES; b++) {
            acc = fmaf(__ldg(&w_comp[r * NUM_BASES + b]),
                       __ldg(&weight[(b << 14) + ko]), acc);
        }
        g_W[gid] = acc;
    }
}

// ---------------------------------------------------------------------------
// K1: out[n] = h_bias + feat[n] @ loop_weight     (initializes d_out)
// blockDim = 512 (16 warps). Each warp handles 8 rows; each lane 4 output
// columns (float4). loop_weight lives in smem (64 KB), feat rows staged in
// smem (64 KB).
// ---------------------------------------------------------------------------
__global__ void __launch_bounds__(512, 1)
selfloop_kernel(const float* __restrict__ feat,
                const float* __restrict__ lw,
                const float* __restrict__ bias,
                float* __restrict__ out,
                int n_nodes) {
    extern __shared__ float smem[];
    float* Ws  = smem;             // 16384 floats (128x128)
    float* fst = smem + 16384;     // 16 warps * 8 rows * 128 floats

    int tid  = threadIdx.x;
    int warp = tid >> 5;
    int lane = tid & 31;

    // Load loop_weight into smem (row-major [k][c])
    {
        const float4* lw4 = (const float4*)lw;
        float4* Ws4w = (float4*)Ws;
        #pragma unroll
        for (int i = tid; i < 4096; i += 512) Ws4w[i] = lw4[i];
    }
    __syncthreads();

    float4 b4 = ((const float4*)bias)[lane];

    int nBase = blockIdx.x * 128 + warp * 8;

    // Stage 8 feat rows for this warp
    float4* fw4 = (float4*)(fst + warp * 1024);
    const float4* feat4 = (const float4*)feat;
    #pragma unroll
    for (int e = 0; e < 8; e++) {
        int n = nBase + e;
        if (n >= n_nodes) n = n_nodes - 1;
        fw4[e * 32 + lane] = feat4[n * 32 + lane];
    }
    __syncwarp();

    float4 acc[8];
    #pragma unroll
    for (int e = 0; e < 8; e++) acc[e] = make_float4(0.f, 0.f, 0.f, 0.f);

    const float4* Ws4 = (const float4*)Ws;
    const float4* fwr = (const float4*)(fst + warp * 1024);

    #pragma unroll 2
    for (int k = 0; k < 128; k += 4) {
        float4 w0 = Ws4[(k + 0) * 32 + lane];
        float4 w1 = Ws4[(k + 1) * 32 + lane];
        float4 w2 = Ws4[(k + 2) * 32 + lane];
        float4 w3 = Ws4[(k + 3) * 32 + lane];
        #pragma unroll
        for (int e = 0; e < 8; e++) {
            float4 f = fwr[e * 32 + (k >> 2)];  // broadcast
            acc[e].x = fmaf(f.x, w0.x, fmaf(f.y, w1.x, fmaf(f.z, w2.x, fmaf(f.w, w3.x, acc[e].x))));
            acc[e].y = fmaf(f.x, w0.y, fmaf(f.y, w1.y, fmaf(f.z, w2.y, fmaf(f.w, w3.y, acc[e].y))));
            acc[e].z = fmaf(f.x, w0.z, fmaf(f.y, w1.z, fmaf(f.z, w2.z, fmaf(f.w, w3.z, acc[e].z))));
            acc[e].w = fmaf(f.x, w0.w, fmaf(f.y, w1.w, fmaf(f.z, w2.w, fmaf(f.w, w3.w, acc[e].w))));
        }
    }

    #pragma unroll
    for (int e = 0; e < 8; e++) {
        int n = nBase + e;
        if (n < n_nodes) {
            float4 o;
            o.x = acc[e].x + b4.x;
            o.y = acc[e].y + b4.y;
            o.z = acc[e].z + b4.z;
            o.w = acc[e].w + b4.w;
            ((float4*)out)[n * 32 + lane] = o;
        }
    }
}

// ---------------------------------------------------------------------------
// K2: edge messages + scatter.
// Each block handles 512 contiguous edges (all one relation, since 512 |
// section). W[rel] (64 KB) in smem. Each warp register-blocks 8 edges x 4
// cols; atomicAdd scatter scaled by norm.
// ---------------------------------------------------------------------------
__global__ void __launch_bounds__(512, 1)
edge_kernel(const float* __restrict__ feat,
            const void* __restrict__ srcv,
            const void* __restrict__ dstv,
            const float* __restrict__ norm,
            float* __restrict__ out,
            int section) {
    extern __shared__ float smem[];
    float* Ws   = smem;                    // 16384 floats
    float* fst  = smem + 16384;            // 16384 floats (16 warps * 1024)
    int*   srcs = (int*)(smem + 32768);    // 16*8
    int*   dsts = srcs + 128;              // 16*8
    float* nrms = (float*)(dsts + 128);    // 16*8

    int tid  = threadIdx.x;
    int warp = tid >> 5;
    int lane = tid & 31;

    int eBlock = blockIdx.x * 512;
    int rel    = eBlock / section;

    // Load this relation's composed weights into smem
    {
        const float4* W4g = (const float4*)(g_W + rel * 16384);
        float4* Ws4w = (float4*)Ws;
        #pragma unroll
        for (int i = tid; i < 4096; i += 512) Ws4w[i] = W4g[i];
    }
    __syncthreads();

    const int s64 = g_src64;
    const int d64 = g_dst64;
    const long long* srcl = (const long long*)srcv;
    const int*       srci = (const int*)srcv;
    const long long* dstl = (const long long*)dstv;
    const int*       dsti = (const int*)dstv;

    const float4* feat4 = (const float4*)feat;
    float4* fw4 = (float4*)(fst + warp * 1024);
    const float4* fwr = (const float4*)(fst + warp * 1024);
    const float4* Ws4 = (const float4*)Ws;
    int*   mysrc = srcs + warp * 8;
    int*   mydst = dsts + warp * 8;
    float* mynrm = nrms + warp * 8;

    // Each warp: 32 contiguous edges, in 4 groups of 8
    #pragma unroll 1
    for (int g = 0; g < 32; g += 8) {
        int e0 = eBlock + warp * 32 + g;

        if (lane < 8) {
            int e = e0 + lane;
            mysrc[lane] = s64 ? (int)srcl[e] : srci[e];
            mydst[lane] = d64 ? (int)dstl[e] : dsti[e];
            mynrm[lane] = norm[e];
        }
        __syncwarp();

        // Stage 8 source feature rows
        #pragma unroll
        for (int e = 0; e < 8; e++) {
            fw4[e * 32 + lane] = feat4[(long)mysrc[e] * 32 + lane];
        }
        __syncwarp();

        float4 acc[8];
        #pragma unroll
        for (int e = 0; e < 8; e++) acc[e] = make_float4(0.f, 0.f, 0.f, 0.f);

        #pragma unroll 2
        for (int k = 0; k < 128; k += 4) {
            float4 w0 = Ws4[(k + 0) * 32 + lane];
            float4 w1 = Ws4[(k + 1) * 32 + lane];
            float4 w2 = Ws4[(k + 2) * 32 + lane];
            float4 w3 = Ws4[(k + 3) * 32 + lane];
            #pragma unroll
            for (int e = 0; e < 8; e++) {
                float4 f = fwr[e * 32 + (k >> 2)];  // broadcast
                acc[e].x = fmaf(f.x, w0.x, fmaf(f.y, w1.x, fmaf(f.z, w2.x, fmaf(f.w, w3.x, acc[e].x))));
                acc[e].y = fmaf(f.x, w0.y, fmaf(f.y, w1.y, fmaf(f.z, w2.y, fmaf(f.w, w3.y, acc[e].y))));
                acc[e].z = fmaf(f.x, w0.z, fmaf(f.y, w1.z, fmaf(f.z, w2.z, fmaf(f.w, w3.z, acc[e].z))));
                acc[e].w = fmaf(f.x, w0.w, fmaf(f.y, w1.w, fmaf(f.z, w2.w, fmaf(f.w, w3.w, acc[e].w))));
            }
        }

        // Scatter (scaled by norm) with atomics
        #pragma unroll
        for (int e = 0; e < 8; e++) {
            float s = mynrm[e];
            float* p = out + (long)mydst[e] * 128 + lane * 4;
            atomicAdd(p + 0, acc[e].x * s);
            atomicAdd(p + 1, acc[e].y * s);
            atomicAdd(p + 2, acc[e].z * s);
            atomicAdd(p + 3, acc[e].w * s);
        }
        __syncwarp();
    }
}

// ---------------------------------------------------------------------------
// K3: relu in place
// ---------------------------------------------------------------------------
__global__ void relu_kernel(float* __restrict__ out, int n4) {
    int i = blockIdx.x * blockDim.x + threadIdx.x;
    if (i < n4) {
        float4 v = ((float4*)out)[i];
        v.x = fmaxf(v.x, 0.f);
        v.y = fmaxf(v.y, 0.f);
        v.z = fmaxf(v.z, 0.f);
        v.w = fmaxf(v.w, 0.f);
        ((float4*)out)[i] = v;
    }
}

// ---------------------------------------------------------------------------
extern "C" void kernel_launch(void* const* d_in, const int* in_sizes, int n_in,
                              void* d_out, int out_size) {
    const float* feat        = (const float*)d_in[0];
    const float* weight      = (const float*)d_in[1];
    const float* w_comp      = (const float*)d_in[2];
    const float* h_bias      = (const float*)d_in[3];
    const float* loop_weight = (const float*)d_in[4];
    const float* norm        = (const float*)d_in[5];
    const void*  src         = d_in[6];
    const void*  dst         = d_in[7];

    const int E       = in_sizes[5];              // norm has E elements
    const int n_nodes = in_sizes[0] / IN_F;       // feat rows
    const int section = E / NUM_RELS;

    float* out = (float*)d_out;

    const int SMEM_SELF = (16384 + 16384) * 4;                 // 128 KB
    const int SMEM_EDGE = (16384 + 16384) * 4 + 128 * 4 * 3;   // ~129.5 KB
    cudaFuncSetAttribute(selfloop_kernel,
                         cudaFuncAttributeMaxDynamicSharedMemorySize, SMEM_SELF);
    cudaFuncSetAttribute(edge_kernel,
                         cudaFuncAttributeMaxDynamicSharedMemorySize, SMEM_EDGE);

    // K0: basis composition + index-width detection
    basis_kernel<<<(NUM_RELS * IN_F * OUT_F + 255) / 256, 256>>>(weight, w_comp, src, dst);

    // K1: out = bias + feat @ loop_weight  (initializes full output)
    int sl_blocks = (n_nodes + 127) / 128;
    selfloop_kernel<<<sl_blocks, 512, SMEM_SELF>>>(feat, loop_weight, h_bias, out, n_nodes);

    // K2: edge messages + atomic scatter
    edge_kernel<<<E / 512, 512, SMEM_EDGE>>>(feat, src, dst, norm, out, section);

    // K3: relu
    relu_kernel<<<(n_nodes * 32 + 255) / 256, 256>>>(out, n_nodes * 32);
}

// round 2
// speedup vs baseline: 1.4697x; 1.4697x over previous
#include <cuda_runtime.h>
#include <stdint.h>

// Problem constants (fixed by the dataset)
#define NUM_RELS   64
#define NUM_BASES  16
#define IN_F       128
#define OUT_F      128
#define N_CAP      100352          // >= n_nodes (100000)

#define ASTR 132                   // A-tile smem stride (floats): conflict-free A frags
#define WSTR 136                   // W-tile smem stride (floats): conflict-free B frags

// Scratch (static device globals; no allocations)
__device__ float g_W[NUM_RELS * IN_F * OUT_F];   // per-relation composed weights, tf32-rounded
__device__ float g_featT[(size_t)N_CAP * IN_F];  // feat, tf32-rounded
__device__ int g_src64;
__device__ int g_dst64;

// ---------------------------------------------------------------------------
// helpers
// ---------------------------------------------------------------------------
__device__ __forceinline__ float f2tf(float f) {
    unsigned u;
    asm("cvt.rna.tf32.f32 %0, %1;" : "=r"(u) : "f"(f));
    return __uint_as_float(u);
}

__device__ __forceinline__ void mma8(float d[4], unsigned a0, unsigned a1,
                                     unsigned a2, unsigned a3,
                                     unsigned b0, unsigned b1) {
    asm("mma.sync.aligned.m16n8k8.row.col.f32.tf32.tf32.f32 "
        "{%0,%1,%2,%3},{%4,%5,%6,%7},{%8,%9},{%0,%1,%2,%3};"
        : "+f"(d[0]), "+f"(d[1]), "+f"(d[2]), "+f"(d[3])
        : "r"(a0), "r"(a1), "r"(a2), "r"(a3), "r"(b0), "r"(b1));
}

#define CP_COMMIT() asm volatile("cp.async.commit_group;" ::: "memory")
#define CP_WAIT(N)  asm volatile("cp.async.wait_group %0;" :: "n"(N) : "memory")

// Warp-tile mainloop: 32x64 output per warp, K=128 in 16 k8 slices.
// As: 128 x ASTR (rows = edges/nodes), Ws: 128 x WSTR ([k][n]).
__device__ __forceinline__ void mma_tile(const float* As, const float* Ws,
                                         int warp, int lane, float acc[2][8][4]) {
    const int gid = lane >> 2, ctg = lane & 3;
    const int wm = warp & 3, wn = warp >> 2;
    const unsigned* Ab = (const unsigned*)As + (wm * 32 + gid) * ASTR + ctg;
    const unsigned* Bb = (const unsigned*)Ws + ctg * WSTR + wn * 64 + gid;
    #pragma unroll
    for (int ks = 0; ks < 16; ks++) {
        unsigned a[2][4];
        unsigned b[8][2];
        #pragma unroll
        for (int mb = 0; mb < 2; mb++) {
            const unsigned* p = Ab + mb * 16 * ASTR + ks * 8;
            a[mb][0] = p[0];
            a[mb][1] = p[8 * ASTR];
            a[mb][2] = p[4];
            a[mb][3] = p[8 * ASTR + 4];
        }
        #pragma unroll
        for (int nt = 0; nt < 8; nt++) {
            const unsigned* p = Bb + ks * 8 * WSTR + nt * 8;
            b[nt][0] = p[0];
            b[nt][1] = p[4 * WSTR];
        }
        #pragma unroll
        for (int mb = 0; mb < 2; mb++)
            #pragma unroll
            for (int nt = 0; nt < 8; nt++)
                mma8(acc[mb][nt], a[mb][0], a[mb][1], a[mb][2], a[mb][3],
                     b[nt][0], b[nt][1]);
    }
}

// ---------------------------------------------------------------------------
// K0: basis composition (tf32-rounded) + index-width detection
// ---------------------------------------------------------------------------
__global__ void basis_kernel(const float* __restrict__ weight,
                             const float* __restrict__ w_comp,
                             const void* __restrict__ srcv,
                             const void* __restrict__ dstv) {
    if (blockIdx.x == 0 && threadIdx.x == 0) {
        const unsigned* s = (const unsigned*)srcv;
        const unsigned* d = (const unsigned*)dstv;
        int s64 = 1, d64 = 1;
        #pragma unroll
        for (int i = 1; i < 32; i += 2) {
            if (s[i] != 0u) s64 = 0;
            if (d[i] != 0u) d64 = 0;
        }
        g_src64 = s64;
        g_dst64 = d64;
    }
    int gid = blockIdx.x * blockDim.x + threadIdx.x;
    if (gid < NUM_RELS * IN_F * OUT_F) {
        int r = gid >> 14;
        int ko = gid & 16383;
        float acc = 0.0f;
        #pragma unroll
        for (int b = 0; b < NUM_BASES; b++)
            acc = fmaf(__ldg(&w_comp[r * NUM_BASES + b]),
                       __ldg(&weight[(b << 14) + ko]), acc);
        g_W[gid] = f2tf(acc);
    }
}

// ---------------------------------------------------------------------------
// K0b: round feat to tf32 into g_featT
// ---------------------------------------------------------------------------
__global__ void round_feat_kernel(const float* __restrict__ feat, int n4) {
    int i = blockIdx.x * blockDim.x + threadIdx.x;
    if (i < n4) {
        float4 v = ((const float4*)feat)[i];
        v.x = f2tf(v.x); v.y = f2tf(v.y); v.z = f2tf(v.z); v.w = f2tf(v.w);
        ((float4*)g_featT)[i] = v;
    }
}

// ---------------------------------------------------------------------------
// K1: self-loop  out[n] = bias + feat[n] @ loop_weight   (tf32 MMA, direct store)
// ---------------------------------------------------------------------------
__global__ void __launch_bounds__(256, 1)
selfloop_mma_kernel(const float* __restrict__ lw,
                    const float* __restrict__ bias,
                    float* __restrict__ out, int n_nodes) {
    extern __shared__ float smem[];
    float* Ws = smem;                    // 128 * WSTR
    float* As = smem + 128 * WSTR;       // 128 * ASTR
    int tid = threadIdx.x, warp = tid >> 5, lane = tid & 31;

    // loop_weight -> smem, tf32-rounded
    const float4* Wg = (const float4*)lw;
    for (int i = tid; i < 4096; i += 256) {
        float4 v = Wg[i];
        v.x = f2tf(v.x); v.y = f2tf(v.y); v.z = f2tf(v.z); v.w = f2tf(v.w);
        int r = i >> 5, c4 = i & 31;
        ((float4*)(Ws + r * WSTR))[c4] = v;
    }

    int nodeBase = blockIdx.x * 128;
    {
        int row = tid >> 1, half = tid & 1;
        int n = nodeBase + row;
        if (n >= n_nodes) n = n_nodes - 1;
        const float4* srow = (const float4*)(g_featT + (long)n * IN_F + half * 64);
        float4* drow = (float4*)(As + row * ASTR + half * 64);
        #pragma unroll
        for (int i = 0; i < 16; i++) drow[i] = srow[i];
    }
    __syncthreads();

    float acc[2][8][4];
    #pragma unroll
    for (int mb = 0; mb < 2; mb++)
        #pragma unroll
        for (int nt = 0; nt < 8; nt++)
            #pragma unroll
            for (int q = 0; q < 4; q++) acc[mb][nt][q] = 0.0f;

    mma_tile(As, Ws, warp, lane, acc);

    const int gid = lane >> 2, ctg = lane & 3;
    const int wm = warp & 3, wn = warp >> 2;
    #pragma unroll
    for (int mb = 0; mb < 2; mb++) {
        #pragma unroll
        for (int nt = 0; nt < 8; nt++) {
            int r = wm * 32 + mb * 16 + gid;
            int c = wn * 64 + nt * 8 + 2 * ctg;
            float2 b2 = *(const float2*)(bias + c);
            int n0 = nodeBase + r;
            if (n0 < n_nodes) {
                float2 o = make_float2(acc[mb][nt][0] + b2.x, acc[mb][nt][1] + b2.y);
                *(float2*)(out + (long)n0 * OUT_F + c) = o;
            }
            int n1 = nodeBase + r + 8;
            if (n1 < n_nodes) {
                float2 o = make_float2(acc[mb][nt][2] + b2.x, acc[mb][nt][3] + b2.y);
                *(float2*)(out + (long)n1 * OUT_F + c) = o;
            }
        }
    }
}

// ---------------------------------------------------------------------------
// K2: edge grouped GEMM + scatter.
// Block = 1024 edges (one relation). W in smem, double-buffered cp.async gather.
// ---------------------------------------------------------------------------
__device__ __forceinline__ void gather_tile(float* Abuf, int* dsts, float* nrms,
                                            const void* srcv, const void* dstv,
                                            const float* norm, long e0,
                                            int s64, int d64, int tid) {
    int row = tid >> 1, half = tid & 1;
    long e = e0 + row;
    long sidx = s64 ? (long)((const long long*)srcv)[e]
                    : (long)((const int*)srcv)[e];
    const float* srow = g_featT + sidx * IN_F + half * 64;
    unsigned daddr =
        (unsigned)__cvta_generic_to_shared(Abuf + row * ASTR + half * 64);
    #pragma unroll
    for (int i = 0; i < 16; i++)
        asm volatile("cp.async.cg.shared.global [%0], [%1], 16;" ::
                     "r"(daddr + i * 16), "l"(srow + i * 4));
    if (tid < 128) {
        long ee = e0 + tid;
        dsts[tid] = d64 ? (int)((const long long*)dstv)[ee]
                        : ((const int*)dstv)[ee];
        nrms[tid] = norm[ee];
    }
}

__global__ void __launch_bounds__(256, 1)
edge_mma_kernel(const void* __restrict__ srcv,
                const void* __restrict__ dstv,
                const float* __restrict__ norm,
                float* __restrict__ out, int section) {
    extern __shared__ float smem[];
    float* Ws = smem;                                  // 128*WSTR = 17408
    float* A0 = smem + 128 * WSTR;                     // 128*ASTR = 16896
    float* A1 = A0 + 128 * ASTR;
    int* dst_s = (int*)(A1 + 128 * ASTR);              // 2*128
    float* norm_s = (float*)(dst_s + 256);             // 2*128

    int tid = threadIdx.x, warp = tid >> 5, lane = tid & 31;
    long eBase = (long)blockIdx.x * 1024;
    int rel = (int)(eBase / section);

    // Load this relation's W into smem (already tf32-rounded)
    const float4* Wg = (const float4*)(g_W + rel * 16384);
    for (int i = tid; i < 4096; i += 256) {
        int r = i >> 5, c4 = i & 31;
        ((float4*)(Ws + r * WSTR))[c4] = Wg[i];
    }

    const int s64 = g_src64, d64 = g_dst64;
    float* Ab[2] = {A0, A1};

    gather_tile(Ab[0], dst_s, norm_s, srcv, dstv, norm, eBase, s64, d64, tid);
    CP_COMMIT();

    const int gid = lane >> 2, ctg = lane & 3;
    const int wm = warp & 3, wn = warp >> 2;

    #pragma unroll 1
    for (int t = 0; t < 8; t++) {
        int cur = t & 1;
        if (t < 7) {
            gather_tile(Ab[cur ^ 1], dst_s + (cur ^ 1) * 128,
                        norm_s + (cur ^ 1) * 128, srcv, dstv, norm,
                        eBase + (long)(t + 1) * 128, s64, d64, tid);
            CP_COMMIT();
            CP_WAIT(1);
        } else {
            CP_WAIT(0);
        }
        __syncthreads();

        float acc[2][8][4];
        #pragma unroll
        for (int mb = 0; mb < 2; mb++)
            #pragma unroll
            for (int nt = 0; nt < 8; nt++)
                #pragma unroll
                for (int q = 0; q < 4; q++) acc[mb][nt][q] = 0.0f;

        float* As = Ab[cur];
        mma_tile(As, Ws, warp, lane, acc);

        __syncthreads();   // everyone done reading As before overwrite

        // accums -> smem (rows = edges)
        #pragma unroll
        for (int mb = 0; mb < 2; mb++) {
            #pragma unroll
            for (int nt = 0; nt < 8; nt++) {
                int r = wm * 32 + mb * 16 + gid;
                int c = wn * 64 + nt * 8 + 2 * ctg;
                *(float2*)&As[r * ASTR + c] =
                    make_float2(acc[mb][nt][0], acc[mb][nt][1]);
                *(float2*)&As[(r + 8) * ASTR + c] =
                    make_float2(acc[mb][nt][2], acc[mb][nt][3]);
            }
        }
        __syncthreads();

        // scatter: warp handles 16 edge rows, vectorized 16B atomics
        const int* mydst = dst_s + cur * 128;
        const float* mynrm = norm_s + cur * 128;
        #pragma unroll
        for (int j = 0; j < 16; j++) {
            int r = warp * 16 + j;
            float nv = mynrm[r];
            long dn = mydst[r];
            float4 v = *(float4*)&As[r * ASTR + lane * 4];
            v.x *= nv; v.y *= nv; v.z *= nv; v.w *= nv;
            atomicAdd((float4*)(out + dn * OUT_F + lane * 4), v);
        }
        __syncthreads();   // scatter done before next gather overwrites As
    }
}

// ---------------------------------------------------------------------------
// K3: relu in place
// ---------------------------------------------------------------------------
__global__ void relu_kernel(float* __restrict__ out, int n4) {
    int i = blockIdx.x * blockDim.x + threadIdx.x;
    if (i < n4) {
        float4 v = ((float4*)out)[i];
        v.x = fmaxf(v.x, 0.f);
        v.y = fmaxf(v.y, 0.f);
        v.z = fmaxf(v.z, 0.f);
        v.w = fmaxf(v.w, 0.f);
        ((float4*)out)[i] = v;
    }
}

// ---------------------------------------------------------------------------
extern "C" void kernel_launch(void* const* d_in, const int* in_sizes, int n_in,
                              void* d_out, int out_size) {
    const float* feat        = (const float*)d_in[0];
    const float* weight      = (const float*)d_in[1];
    const float* w_comp      = (const float*)d_in[2];
    const float* h_bias      = (const float*)d_in[3];
    const float* loop_weight = (const float*)d_in[4];
    const float* norm        = (const float*)d_in[5];
    const void*  src         = d_in[6];
    const void*  dst         = d_in[7];

    const int E       = in_sizes[5];
    const int n_nodes = in_sizes[0] / IN_F;
    const int section = E / NUM_RELS;

    float* out = (float*)d_out;

    const int SMEM_SELF = (128 * WSTR + 128 * ASTR) * 4;                     // ~134 KB
    const int SMEM_EDGE = (128 * WSTR + 2 * 128 * ASTR) * 4 + 256 * 4 * 2;   // ~202 KB
    cudaFuncSetAttribute(selfloop_mma_kernel,
                         cudaFuncAttributeMaxDynamicSharedMemorySize, SMEM_SELF);
    cudaFuncSetAttribute(edge_mma_kernel,
                         cudaFuncAttributeMaxDynamicSharedMemorySize, SMEM_EDGE);

    // K0: basis composition + index detect
    basis_kernel<<<(NUM_RELS * IN_F * OUT_F + 255) / 256, 256>>>(weight, w_comp, src, dst);

    // K0b: round feat to tf32
    int n4 = n_nodes * (IN_F / 4);
    round_feat_kernel<<<(n4 + 255) / 256, 256>>>(feat, n4);

    // K1: self-loop (initializes out)
    int sl_blocks = (n_nodes + 127) / 128;
    selfloop_mma_kernel<<<sl_blocks, 256, SMEM_SELF>>>(loop_weight, h_bias, out, n_nodes);

    // K2: edge grouped GEMM + scatter
    edge_mma_kernel<<<E / 1024, 256, SMEM_EDGE>>>(src, dst, norm, out, section);

    // K3: relu
    relu_kernel<<<(n_nodes * (OUT_F / 4) + 255) / 256, 256>>>(out, n_nodes * (OUT_F / 4));
}

// round 9
// speedup vs baseline: 1.5390x; 1.0471x over previous
#include <cuda_runtime.h>
#include <stdint.h>

// Problem constants (fixed by the dataset)
#define NUM_RELS   64
#define NUM_BASES  16
#define IN_F       128
#define OUT_F      128
#define N_CAP      100352          // >= n_nodes (100000)

#define ASTR 132                   // A-tile smem stride (floats)
#define WSTR 136                   // W-tile smem stride (floats)

// Scratch (static device globals; no allocations)
__device__ float g_W[NUM_RELS * IN_F * OUT_F];   // per-relation weights, tf32-rounded, [r][k][o]
__device__ float g_featT[(size_t)N_CAP * IN_F];  // feat, tf32-rounded
__device__ int g_src64;
__device__ int g_dst64;

// ---------------------------------------------------------------------------
// helpers
// ---------------------------------------------------------------------------
__device__ __forceinline__ float f2tf(float f) {
    unsigned u;
    asm("cvt.rna.tf32.f32 %0, %1;" : "=r"(u) : "f"(f));
    return __uint_as_float(u);
}

__device__ __forceinline__ void mma8(float d[4], unsigned a0, unsigned a1,
                                     unsigned a2, unsigned a3,
                                     unsigned b0, unsigned b1) {
    asm("mma.sync.aligned.m16n8k8.row.col.f32.tf32.tf32.f32 "
        "{%0,%1,%2,%3},{%4,%5,%6,%7},{%8,%9},{%0,%1,%2,%3};"
        : "+f"(d[0]), "+f"(d[1]), "+f"(d[2]), "+f"(d[3])
        : "r"(a0), "r"(a1), "r"(a2), "r"(a3), "r"(b0), "r"(b1));
}

#define CP_COMMIT() asm volatile("cp.async.commit_group;" ::: "memory")
#define CP_WAIT(N)  asm volatile("cp.async.wait_group %0;" :: "n"(N) : "memory")

// Single extern-shared symbol for the whole TU
extern __shared__ char smem_c[];

// Warp-tile mainloop: 32x64 output per warp, K=128 in 16 k8 slices.
__device__ __forceinline__ void mma_tile(const float* As, const float* Ws,
                                         int warp, int lane, float acc[2][8][4]) {
    const int gid = lane >> 2, ctg = lane & 3;
    const int wm = warp & 3, wn = warp >> 2;
    const unsigned* Ab = (const unsigned*)As + (wm * 32 + gid) * ASTR + ctg;
    const unsigned* Bb = (const unsigned*)Ws + ctg * WSTR + wn * 64 + gid;
    #pragma unroll
    for (int ks = 0; ks < 16; ks++) {
        unsigned a[2][4], b[8][2];
        #pragma unroll
        for (int mb = 0; mb < 2; mb++) {
            const unsigned* p = Ab + mb * 16 * ASTR + ks * 8;
            a[mb][0] = p[0];
            a[mb][1] = p[8 * ASTR];
            a[mb][2] = p[4];
            a[mb][3] = p[8 * ASTR + 4];
        }
        #pragma unroll
        for (int nt = 0; nt < 8; nt++) {
            const unsigned* p = Bb + ks * 8 * WSTR + nt * 8;
            b[nt][0] = p[0];
            b[nt][1] = p[4 * WSTR];
        }
        #pragma unroll
        for (int mb = 0; mb < 2; mb++)
            #pragma unroll
            for (int nt = 0; nt < 8; nt++)
                mma8(acc[mb][nt], a[mb][0], a[mb][1], a[mb][2], a[mb][3],
                     b[nt][0], b[nt][1]);
    }
}

// ---------------------------------------------------------------------------
// K0: basis composition  W[r][k][o]  (tf32-rounded) + index-width detection
// ---------------------------------------------------------------------------
__global__ void basis_kernel(const float* __restrict__ weight,
                             const float* __restrict__ w_comp,
                             const void* __restrict__ srcv,
                             const void* __restrict__ dstv) {
    if (blockIdx.x == 0 && threadIdx.x == 0) {
        const unsigned* s = (const unsigned*)srcv;
        const unsigned* d = (const unsigned*)dstv;
        int s64 = 1, d64 = 1;
        #pragma unroll
        for (int i = 1; i < 32; i += 2) {
            if (s[i] != 0u) s64 = 0;
            if (d[i] != 0u) d64 = 0;
        }
        g_src64 = s64;
        g_dst64 = d64;
    }
    int gid = blockIdx.x * blockDim.x + threadIdx.x;
    if (gid < NUM_RELS * IN_F * OUT_F) {
        int r = gid >> 14;
        int ko = gid & 16383;
        float acc = 0.0f;
        #pragma unroll
        for (int b = 0; b < NUM_BASES; b++)
            acc = fmaf(__ldg(&w_comp[r * NUM_BASES + b]),
                       __ldg(&weight[(b << 14) + ko]), acc);
        g_W[gid] = f2tf(acc);
    }
}

// ---------------------------------------------------------------------------
// K0b: round feat to tf32 into g_featT
// ---------------------------------------------------------------------------
__global__ void round_feat_kernel(const float* __restrict__ feat, int n4) {
    int i = blockIdx.x * blockDim.x + threadIdx.x;
    if (i < n4) {
        float4 v = ((const float4*)feat)[i];
        v.x = f2tf(v.x); v.y = f2tf(v.y); v.z = f2tf(v.z); v.w = f2tf(v.w);
        ((float4*)g_featT)[i] = v;
    }
}

// ---------------------------------------------------------------------------
// K1: self-loop  out[n] = bias + feat[n] @ loop_weight   (tf32 MMA)
// ---------------------------------------------------------------------------
__global__ void __launch_bounds__(256, 1)
selfloop_mma_kernel(const float* __restrict__ lw,
                    const float* __restrict__ bias,
                    float* __restrict__ out, int n_nodes) {
    float* smem = (float*)smem_c;
    float* Ws = smem;                    // 128 * WSTR
    float* As = smem + 128 * WSTR;       // 128 * ASTR
    int tid = threadIdx.x, warp = tid >> 5, lane = tid & 31;

    const float4* Wg = (const float4*)lw;
    for (int i = tid; i < 4096; i += 256) {
        float4 v = Wg[i];
        v.x = f2tf(v.x); v.y = f2tf(v.y); v.z = f2tf(v.z); v.w = f2tf(v.w);
        int r = i >> 5, c4 = i & 31;
        ((float4*)(Ws + r * WSTR))[c4] = v;
    }

    int nodeBase = blockIdx.x * 128;
    {
        int row = tid >> 1, half = tid & 1;
        int n = nodeBase + row;
        if (n >= n_nodes) n = n_nodes - 1;
        const float4* srow = (const float4*)(g_featT + (long)n * IN_F + half * 64);
        float4* drow = (float4*)(As + row * ASTR + half * 64);
        #pragma unroll
        for (int i = 0; i < 16; i++) drow[i] = srow[i];
    }
    __syncthreads();

    float acc[2][8][4];
    #pragma unroll
    for (int mb = 0; mb < 2; mb++)
        #pragma unroll
        for (int nt = 0; nt < 8; nt++)
            #pragma unroll
            for (int q = 0; q < 4; q++) acc[mb][nt][q] = 0.0f;

    mma_tile(As, Ws, warp, lane, acc);

    const int gid = lane >> 2, ctg = lane & 3;
    const int wm = warp & 3, wn = warp >> 2;
    #pragma unroll
    for (int mb = 0; mb < 2; mb++) {
        #pragma unroll
        for (int nt = 0; nt < 8; nt++) {
            int r = wm * 32 + mb * 16 + gid;
            int c = wn * 64 + nt * 8 + 2 * ctg;
            float2 b2 = *(const float2*)(bias + c);
            int n0 = nodeBase + r;
            if (n0 < n_nodes)
                *(float2*)(out + (long)n0 * OUT_F + c) =
                    make_float2(acc[mb][nt][0] + b2.x, acc[mb][nt][1] + b2.y);
            int n1 = nodeBase + r + 8;
            if (n1 < n_nodes)
                *(float2*)(out + (long)n1 * OUT_F + c) =
                    make_float2(acc[mb][nt][2] + b2.x, acc[mb][nt][3] + b2.y);
        }
    }
}

// ---------------------------------------------------------------------------
// K2: edge grouped GEMM + scatter — pipelined, fragment-direct epilogue.
// Block = 1024 edges (one relation), 8 tiles of 128, double-buffered cp.async.
// smem floats: W 0..17407 | A0 17408.. | A1 34304.. | dst 51200 | nrm 51712
// ---------------------------------------------------------------------------
#define EDGE_SMEM_FLOATS 52224

__device__ __forceinline__ void gather_tile(float* Abuf, int* dsts, float* nrms,
                                            const void* srcv, const void* dstv,
                                            const float* norm, long e0,
                                            int s64, int d64, int tid) {
    int row = tid >> 1, half = tid & 1;
    long e = e0 + row;
    long sidx = s64 ? (long)((const long long*)srcv)[e]
                    : (long)((const int*)srcv)[e];
    const float* srow = g_featT + sidx * IN_F + half * 64;
    unsigned daddr =
        (unsigned)__cvta_generic_to_shared(Abuf + row * ASTR + half * 64);
    #pragma unroll
    for (int i = 0; i < 16; i++)
        asm volatile("cp.async.cg.shared.global [%0], [%1], 16;" ::
                     "r"(daddr + i * 16), "l"(srow + i * 4));
    if (tid < 128) {
        long ee = e0 + tid;
        dsts[tid] = d64 ? (int)((const long long*)dstv)[ee]
                        : ((const int*)dstv)[ee];
        nrms[tid] = norm[ee];
    }
}

__global__ void __launch_bounds__(256, 1)
edge_mma_kernel(const void* __restrict__ srcv,
                const void* __restrict__ dstv,
                const float* __restrict__ norm,
                float* __restrict__ out, int section) {
    float* smem = (float*)smem_c;
    float* Ws = smem;
    float* A0 = smem + 17408;
    float* A1 = smem + 34304;
    int*   dst_s = (int*)(smem + 51200);     // [2][128]
    float* nrm_s = smem + 51712;             // [2][128]

    int tid = threadIdx.x, warp = tid >> 5, lane = tid & 31;
    long eBase = (long)blockIdx.x * 1024;
    int rel = (int)(eBase / section);

    // Prologue: W (cp.async) + gather tile0 -> buf0, one commit group.
    {
        const float* Wg = g_W + (size_t)rel * 16384;
        for (int i = tid; i < 4096; i += 256) {
            int r = i >> 5, c4 = i & 31;
            unsigned daddr = (unsigned)__cvta_generic_to_shared(
                (float4*)(Ws + r * WSTR) + c4);
            asm volatile("cp.async.cg.shared.global [%0], [%1], 16;" ::
                         "r"(daddr), "l"(Wg + i * 4));
        }
    }
    const int s64 = g_src64, d64 = g_dst64;
    gather_tile(A0, dst_s, nrm_s, srcv, dstv, norm, eBase, s64, d64, tid);
    CP_COMMIT();

    const int gid = lane >> 2, ctg = lane & 3;
    const int wm = warp & 3, wn = warp >> 2;
    float* Ab[2] = {A0, A1};

    #pragma unroll 1
    for (int t = 0; t < 8; t++) {
        int b = t & 1;
        __syncthreads();   // protect buf b^1 (readers from iter t-1 done)
        if (t < 7) {
            gather_tile(Ab[b ^ 1], dst_s + (b ^ 1) * 128,
                        nrm_s + (b ^ 1) * 128, srcv, dstv, norm,
                        eBase + (long)(t + 1) * 128, s64, d64, tid);
            CP_COMMIT();
            CP_WAIT(1);    // buf b's group complete
        } else {
            CP_WAIT(0);
        }
        __syncthreads();   // all threads' gathers for buf b visible

        float acc[2][8][4];
        #pragma unroll
        for (int mb = 0; mb < 2; mb++)
            #pragma unroll
            for (int nt = 0; nt < 8; nt++)
                #pragma unroll
                for (int q = 0; q < 4; q++) acc[mb][nt][q] = 0.0f;

        mma_tile(Ab[b], Ws, warp, lane, acc);

        // Fragment-direct epilogue: scale by norm, shfl-merge lane pairs,
        // half-warp float4 atomics. No smem writeback, no barrier.
        const int* mydst = dst_s + b * 128;
        const float* mynrm = nrm_s + b * 128;
        #pragma unroll
        for (int mb = 0; mb < 2; mb++) {
            int r0 = wm * 32 + mb * 16 + gid;
            int r1 = r0 + 8;
            float nv0 = mynrm[r0], nv1 = mynrm[r1];
            long d0 = mydst[r0], d1 = mydst[r1];
            #pragma unroll
            for (int nt = 0; nt < 8; nt++) {
                float x0 = acc[mb][nt][0] * nv0, x1 = acc[mb][nt][1] * nv0;
                float x2 = acc[mb][nt][2] * nv1, x3 = acc[mb][nt][3] * nv1;
                float y0 = __shfl_xor_sync(0xFFFFFFFFu, x0, 1);
                float y1 = __shfl_xor_sync(0xFFFFFFFFu, x1, 1);
                float y2 = __shfl_xor_sync(0xFFFFFFFFu, x2, 1);
                float y3 = __shfl_xor_sync(0xFFFFFFFFu, x3, 1);
                if (!(lane & 1)) {   // ctg even: owns cols 2ctg..2ctg+3
                    int c = wn * 64 + nt * 8 + 2 * ctg;
                    atomicAdd((float4*)(out + d0 * OUT_F + c),
                              make_float4(x0, x1, y0, y1));
                    atomicAdd((float4*)(out + d1 * OUT_F + c),
                              make_float4(x2, x3, y2, y3));
                }
            }
        }
    }
}

// ---------------------------------------------------------------------------
// K3: relu in place
// ---------------------------------------------------------------------------
__global__ void relu_kernel(float* __restrict__ out, int n4) {
    int i = blockIdx.x * blockDim.x + threadIdx.x;
    if (i < n4) {
        float4 v = ((float4*)out)[i];
        v.x = fmaxf(v.x, 0.f);
        v.y = fmaxf(v.y, 0.f);
        v.z = fmaxf(v.z, 0.f);
        v.w = fmaxf(v.w, 0.f);
        ((float4*)out)[i] = v;
    }
}

// ---------------------------------------------------------------------------
extern "C" void kernel_launch(void* const* d_in, const int* in_sizes, int n_in,
                              void* d_out, int out_size) {
    const float* feat        = (const float*)d_in[0];
    const float* weight      = (const float*)d_in[1];
    const float* w_comp      = (const float*)d_in[2];
    const float* h_bias      = (const float*)d_in[3];
    const float* loop_weight = (const float*)d_in[4];
    const float* norm        = (const float*)d_in[5];
    const void*  src         = d_in[6];
    const void*  dst         = d_in[7];

    const int E       = in_sizes[5];
    const int n_nodes = in_sizes[0] / IN_F;
    const int section = E / NUM_RELS;

    float* out = (float*)d_out;

    const int SMEM_SELF = (128 * WSTR + 128 * ASTR) * 4;   // ~134 KB
    const int SMEM_EDGE = EDGE_SMEM_FLOATS * 4;            // ~204 KB
    cudaFuncSetAttribute(selfloop_mma_kernel,
                         cudaFuncAttributeMaxDynamicSharedMemorySize, SMEM_SELF);
    cudaFuncSetAttribute(edge_mma_kernel,
                         cudaFuncAttributeMaxDynamicSharedMemorySize, SMEM_EDGE);

    // K0: basis composition + index detect
    basis_kernel<<<(NUM_RELS * IN_F * OUT_F + 255) / 256, 256>>>(weight, w_comp, src, dst);

    // K0b: round feat to tf32
    int n4 = n_nodes * (IN_F / 4);
    round_feat_kernel<<<(n4 + 255) / 256, 256>>>(feat, n4);

    // K1: self-loop (initializes out)
    selfloop_mma_kernel<<<(n_nodes + 127) / 128, 256, SMEM_SELF>>>(loop_weight, h_bias, out, n_nodes);

    // K2: edge grouped GEMM + scatter
    edge_mma_kernel<<<E / 1024, 256, SMEM_EDGE>>>(src, dst, norm, out, section);

    // K3: relu
    relu_kernel<<<(n_nodes * (OUT_F / 4) + 255) / 256, 256>>>(out, n_nodes * (OUT_F / 4));
}